// round 6
// baseline (speedup 1.0000x reference)
#include <cuda_runtime.h>
#include <math.h>

#define N_ENT 100000
#define N_REL 64
#define E_DIM 64
#define KNB   32
#define BSZ   1024

typedef unsigned long long ull;

// Device scratch (no allocation allowed)
__device__ float  d_scale[N_ENT];            // per-entity normalization scale
__device__ float  d_RW[N_REL * E_DIM];       // RW[rel][f] = Rnorm[rel] . w1r[f]
__device__ float2 d_W2P[E_DIM * 32];         // d_W2P[f*32+q] = (w2[q][f], w2[q+32][f])

__device__ __forceinline__ float leaky(float x) { return x >= 0.f ? x : 0.2f * x; }

__device__ __forceinline__ ull ffma2(ull a, ull b, ull c) {
    ull d;
    asm("fma.rn.f32x2 %0, %1, %2, %3;" : "=l"(d) : "l"(a), "l"(b), "l"(c));
    return d;
}
__device__ __forceinline__ ull packdup(float x) {
    ull d;
    asm("mov.b64 %0, {%1, %1};" : "=l"(d) : "f"(x));
    return d;
}

// ---------------------------------------------------------------------------
// prep kernel: blocks [0, NB_NORM) compute per-entity scales (2 rows ILP per
// thread); the LAST block normalizes R, builds RW and pre-pairs W2.
// ---------------------------------------------------------------------------
#define ROWS_PER_BLK 32
#define NB_NORM ((N_ENT + ROWS_PER_BLK - 1) / ROWS_PER_BLK)

__global__ void __launch_bounds__(256) prep_kernel(const float* __restrict__ E,
                                                   const float* __restrict__ R,
                                                   const float* __restrict__ w1,
                                                   const float* __restrict__ w2) {
    int tid = threadIdx.x, w = tid >> 5, lane = tid & 31;

    if (blockIdx.x < NB_NORM) {
        // 256 threads, 16 row-groups of 16 lanes; each thread handles 2 rows
        int l = tid & 15;
        int rg = tid >> 4;                 // 0..15
        int rowA = blockIdx.x * ROWS_PER_BLK + rg;
        int rowB = rowA + 16;
        float4 vA = make_float4(0, 0, 0, 0), vB = make_float4(0, 0, 0, 0);
        if (rowA < N_ENT) vA = ((const float4*)(E + (size_t)rowA * E_DIM))[l];
        if (rowB < N_ENT) vB = ((const float4*)(E + (size_t)rowB * E_DIM))[l];
        float sA = vA.x * vA.x + vA.y * vA.y + vA.z * vA.z + vA.w * vA.w;
        float sB = vB.x * vB.x + vB.y * vB.y + vB.z * vB.z + vB.w * vB.w;
        #pragma unroll
        for (int o = 8; o > 0; o >>= 1) {
            sA += __shfl_xor_sync(0xffffffffu, sA, o);
            sB += __shfl_xor_sync(0xffffffffu, sB, o);
        }
        if (l == 0) {
            if (rowA < N_ENT) {
                float n = sqrtf(sA);
                d_scale[rowA] = (n > 1.0f) ? 1.0f / (n + 1e-7f) : 1.0f;
            }
            if (rowB < N_ENT) {
                float n = sqrtf(sB);
                d_scale[rowB] = (n > 1.0f) ? 1.0f / (n + 1e-7f) : 1.0f;
            }
        }
        return;
    }

    // ---- prepRW block ----
    __shared__ float Rn[N_REL * E_DIM];       // 16 KB
    __shared__ float w1rT[E_DIM * 65];
    #pragma unroll
    for (int k = 0; k < 8; k++) {
        int row = w * 8 + k;
        float2 v = ((const float2*)(R + row * E_DIM))[lane];
        float ss = v.x * v.x + v.y * v.y;
        #pragma unroll
        for (int o = 16; o > 0; o >>= 1) ss += __shfl_xor_sync(0xffffffffu, ss, o);
        float n = sqrtf(ss);
        float sc = (n > 1.0f) ? 1.0f / (n + 1e-7f) : 1.0f;
        Rn[row * E_DIM + lane * 2]     = v.x * sc;
        Rn[row * E_DIM + lane * 2 + 1] = v.y * sc;
    }
    for (int i = tid; i < E_DIM * E_DIM; i += 256) {
        int f = i >> 6, e = i & 63;
        w1rT[e * 65 + f] = w1[f * 128 + 64 + e];
    }
    #pragma unroll
    for (int j = 0; j < 8; j++) {
        int i = tid + j * 256;               // i = f*32+q
        int f = i >> 5, q = i & 31;
        d_W2P[i] = make_float2(w2[q * E_DIM + f], w2[(q + 32) * E_DIM + f]);
    }
    __syncthreads();
    #pragma unroll
    for (int j = 0; j < 16; j++) {
        int i = tid + j * 256;
        int rel = i >> 6, f = i & 63;
        float s = 0.f;
        #pragma unroll
        for (int e = 0; e < E_DIM; e++) s += Rn[rel * E_DIM + e] * w1rT[e * 65 + f];
        d_RW[rel * E_DIM + f] = s;
    }
}

// ---------------------------------------------------------------------------
// Fused per-root kernel. One block (256 threads) per root. smem <= 27 KB
// so 8 CTAs/SM (full 2048-thread occupancy).
// Entries: 0..31 = hop-1 neighbors (query hWh), 32..95 = hop-2 rels (hWs).
// Scratch union timeline (strictly ordered by __syncthreads):
//   [0..3072) hidAll (GEMM)  ->  [2112..2880) scoreP  ->
//   [1088..2112) wS (per-neighbor weights)  ->  [0..1088) gather partials
// ---------------------------------------------------------------------------
__global__ void __launch_bounds__(256) fused_kernel(
        const int* __restrict__ entity_idx,
        const int* __restrict__ adj_e,
        const int* __restrict__ adj_r,
        const float* __restrict__ E,
        const float* __restrict__ w1,
        const float* __restrict__ w3,
        const float* __restrict__ wxw,
        const float* __restrict__ wxb,
        const float* __restrict__ wcw,
        const float* __restrict__ wcb,
        float* __restrict__ out) {
    int b = blockIdx.x;
    int tid = threadIdx.x, w = tid >> 5, lane = tid & 31;

    __shared__ float  t1[KNB * E_DIM];          // 8 KB (normalized hop-1 rows)
    __shared__ int    idx2[KNB * KNB];          // 4 KB: idx | (rel<<20)
    __shared__ float  scratch[3072];            // 12 KB union (see header)
    __shared__ float  eaAll[96];
    __shared__ float  hS[E_DIM], hsumS[E_DIM];
    __shared__ float  hWh[E_DIM], hWs[E_DIM];
    __shared__ float  aggS[E_DIM], vS[E_DIM];
    __shared__ int    ent1[KNB], rel1[KNB];
    __shared__ float  red8[8];
    __shared__ float  sS1, sS2;

    float* hidAll = scratch;                    // [0..3072), pitch 96
    float* scoreP = scratch + 2112;             // [2112..2880), 8*96
    float* wS     = scratch + 1088;             // [1088..2112)
    float* part   = scratch;                    // [0..1088), 16*68

    int eidx = entity_idx[b];
    // ---- Phase A: root loads ----
    if (tid < KNB) {
        ent1[tid] = adj_e[eidx * KNB + tid];
        rel1[tid] = adj_r[eidx * KNB + tid];
    }
    if (tid < E_DIM) hS[tid] = E[(size_t)eidx * E_DIM + tid] * __ldg(&d_scale[eidx]);
    __syncthreads();

    // ---- Phase B: hop-2 packed indices + normalized t1 rows ----
    for (int i = tid; i < KNB * KNB; i += 256) {
        int e1 = ent1[i >> 5];
        int id = adj_e[e1 * KNB + (i & 31)];
        int rl = adj_r[e1 * KNB + (i & 31)];
        idx2[i] = id | (rl << 20);
    }
    for (int i = tid; i < KNB * E_DIM; i += 256) {
        int n = i >> 6, e = i & 63;
        int id = ent1[n];
        t1[i] = E[(size_t)id * E_DIM + e] * __ldg(&d_scale[id]);
    }
    __syncthreads();

    // ---- hsum ----
    if (tid < E_DIM) {
        float s = 0.f;
        #pragma unroll
        for (int n = 0; n < KNB; n++) s += t1[n * E_DIM + tid];
        hsumS[tid] = s;
    }
    __syncthreads();

    // ---- query projections ----
    #pragma unroll
    for (int k = 0; k < 16; k++) {
        int job = w * 16 + k;
        int f = job & 63;
        const float* q = (job < 64) ? hS : hsumS;
        float2 wv = ((const float2*)(w1 + f * 128))[lane];
        float p = wv.x * q[lane * 2] + wv.y * q[lane * 2 + 1];
        #pragma unroll
        for (int o = 16; o > 0; o >>= 1) p += __shfl_down_sync(0xffffffffu, p, o);
        if (lane == 0) { if (job < 64) hWh[f] = p; else hWs[f] = p; }
    }
    __syncthreads();

    // ---- score GEMM: thread (w,lane) owns 4 o-pairs x 3 entries, f32x2 math
    ull acc[4][3];
    #pragma unroll
    for (int q = 0; q < 4; q++)
        #pragma unroll
        for (int j = 0; j < 3; j++) acc[q][j] = 0ull;

    const ull* W2u = (const ull*)d_W2P;
    int e0 = lane * 3;
    #pragma unroll
    for (int p = 0; p < 2; p++) {
        if (tid < 192) {
            int entry = tid >> 1, fh = tid & 1;
            int rel = (entry < KNB) ? rel1[entry] : (entry - KNB);
            const float* qv = (entry < KNB) ? hWh : hWs;
            #pragma unroll
            for (int j = 0; j < 16; j++) {
                int fl = fh * 16 + j;
                int f = p * 32 + fl;
                float x = qv[f] + __ldg(&d_RW[rel * E_DIM + f]);
                hidAll[fl * 96 + entry] = x > 0.f ? x : 0.f;
            }
        }
        __syncthreads();
        #pragma unroll
        for (int fl = 0; fl < 32; fl++) {
            int f = p * 32 + fl;
            ull w0 = __ldg(&W2u[f * 32 + w * 4 + 0]);
            ull w1v = __ldg(&W2u[f * 32 + w * 4 + 1]);
            ull w2v = __ldg(&W2u[f * 32 + w * 4 + 2]);
            ull w3v = __ldg(&W2u[f * 32 + w * 4 + 3]);
            ull h0 = packdup(hidAll[fl * 96 + e0]);
            ull h1 = packdup(hidAll[fl * 96 + e0 + 1]);
            ull h2 = packdup(hidAll[fl * 96 + e0 + 2]);
            acc[0][0] = ffma2(w0, h0, acc[0][0]);
            acc[0][1] = ffma2(w0, h1, acc[0][1]);
            acc[0][2] = ffma2(w0, h2, acc[0][2]);
            acc[1][0] = ffma2(w1v, h0, acc[1][0]);
            acc[1][1] = ffma2(w1v, h1, acc[1][1]);
            acc[1][2] = ffma2(w1v, h2, acc[1][2]);
            acc[2][0] = ffma2(w2v, h0, acc[2][0]);
            acc[2][1] = ffma2(w2v, h1, acc[2][1]);
            acc[2][2] = ffma2(w2v, h2, acc[2][2]);
            acc[3][0] = ffma2(w3v, h0, acc[3][0]);
            acc[3][1] = ffma2(w3v, h1, acc[3][1]);
            acc[3][2] = ffma2(w3v, h2, acc[3][2]);
        }
        __syncthreads();
    }

    // ---- relu + w3 dot, per-warp partials ----
    {
        float w3v[4], w3u[4];
        #pragma unroll
        for (int q = 0; q < 4; q++) {
            int o = w * 4 + q;
            w3v[q] = __ldg(&w3[o]);
            w3u[q] = __ldg(&w3[o + 32]);
        }
        #pragma unroll
        for (int j = 0; j < 3; j++) {
            float s = 0.f;
            #pragma unroll
            for (int q = 0; q < 4; q++) {
                ull a = acc[q][j];
                float g0 = __uint_as_float((unsigned)(a & 0xffffffffull));
                float g1 = __uint_as_float((unsigned)(a >> 32));
                g0 = g0 > 0.f ? g0 : 0.f;
                g1 = g1 > 0.f ? g1 : 0.f;
                s += w3v[q] * g0 + w3u[q] * g1;
            }
            scoreP[w * 96 + e0 + j] = s;
        }
    }
    __syncthreads();
    if (tid < 96) {
        float c = 0.f;
        #pragma unroll
        for (int ww = 0; ww < 8; ww++) c += scoreP[ww * 96 + tid];
        eaAll[tid] = expf(1.f / (1.f + expf(-c)));
    }
    __syncthreads();

    // ---- per-neighbor combined weights wS[n] = ea[rel]*scale[idx]; S2 = sum ea
    {
        float sp = 0.f;
        #pragma unroll
        for (int j = 0; j < 4; j++) {
            int i = tid * 4 + j;
            int v = idx2[i];
            int rl = v >> 20, id = v & 0xFFFFF;
            float ea = eaAll[32 + rl];
            wS[i] = ea * __ldg(&d_scale[id]);
            sp += ea;
        }
        #pragma unroll
        for (int o = 16; o > 0; o >>= 1) sp += __shfl_down_sync(0xffffffffu, sp, o);
        if (lane == 0) red8[w] = sp;
    }
    __syncthreads();
    if (tid == 0) {
        float s = 0.f;
        #pragma unroll
        for (int i = 0; i < 8; i++) s += red8[i];
        sS2 = s;
    }
    __syncthreads();      // also guards part region (aliases nothing live now)

    // ---- hop-2 weighted gather: 2 LDS + 1 LDG.128 + 4 FMA per neighbor ----
    {
        const float4* E4 = (const float4*)E;
        int seg = tid & 15, r = tid >> 4;
        float4 gacc = make_float4(0.f, 0.f, 0.f, 0.f);
        #pragma unroll
        for (int base = 0; base < KNB * KNB; base += 128) {
            int   ids[8];
            float ws[8];
            float4 vs[8];
            #pragma unroll
            for (int u8 = 0; u8 < 8; u8++) {
                int n = base + u8 * 16 + r;
                ids[u8] = idx2[n] & 0xFFFFF;
                ws[u8] = wS[n];
            }
            #pragma unroll
            for (int u8 = 0; u8 < 8; u8++)
                vs[u8] = __ldg(&E4[(size_t)ids[u8] * 16 + seg]);
            #pragma unroll
            for (int u8 = 0; u8 < 8; u8++) {
                gacc.x += ws[u8] * vs[u8].x; gacc.y += ws[u8] * vs[u8].y;
                gacc.z += ws[u8] * vs[u8].z; gacc.w += ws[u8] * vs[u8].w;
            }
        }
        ((float4*)(part + r * 68))[seg] = gacc;
    }

    // ---- hop-1 aggregation ----
    if (tid < E_DIM) {
        float ag = 0.f;
        #pragma unroll
        for (int n = 0; n < KNB; n++) ag += eaAll[n] * t1[n * E_DIM + tid];
        aggS[tid] = ag;
    }
    if (tid >= 64 && tid < 96) {
        int l2 = tid - 64;
        float e = eaAll[l2];
        #pragma unroll
        for (int o = 16; o > 0; o >>= 1) e += __shfl_down_sync(0xffffffffu, e, o);
        if (l2 == 0) sS1 = e;
    }
    __syncthreads();
    if (tid < E_DIM) aggS[tid] /= sS1;
    __syncthreads();

    // ---- hop-1 epilogue ----
    #pragma unroll
    for (int k = 0; k < 8; k++) {
        int o = w * 8 + k;
        float2 wv = ((const float2*)(wxw + o * E_DIM))[lane];
        float p = wv.x * aggS[lane * 2] + wv.y * aggS[lane * 2 + 1];
        #pragma unroll
        for (int off = 16; off > 0; off >>= 1) p += __shfl_down_sync(0xffffffffu, p, off);
        if (lane == 0) vS[o] = leaky(p + wxb[o]);
    }
    __syncthreads();
    #pragma unroll
    for (int k = 0; k < 8; k++) {
        int o = w * 8 + k;
        float4 wv = ((const float4*)(wcw + o * 128))[lane];
        int i0 = lane * 4;
        float x0 = (i0 < 64)     ? hS[i0]     : vS[i0 - 64];
        float x1 = (i0 + 1 < 64) ? hS[i0 + 1] : vS[i0 - 63];
        float x2 = (i0 + 2 < 64) ? hS[i0 + 2] : vS[i0 - 62];
        float x3 = (i0 + 3 < 64) ? hS[i0 + 3] : vS[i0 - 61];
        float p = wv.x * x0 + wv.y * x1 + wv.z * x2 + wv.w * x3;
        #pragma unroll
        for (int off = 16; off > 0; off >>= 1) p += __shfl_down_sync(0xffffffffu, p, off);
        if (lane == 0) out[b * 192 + 64 + o] = leaky(p + wcb[o]);
    }
    if (tid < E_DIM) out[b * 192 + 128 + tid] = hS[tid];
    __syncthreads();

    // ---- hop-2 epilogue ----
    if (tid < E_DIM) {
        float s = 0.f;
        #pragma unroll
        for (int r = 0; r < 16; r++) s += part[r * 68 + tid];
        aggS[tid] = s / sS2;
    }
    __syncthreads();
    #pragma unroll
    for (int k = 0; k < 8; k++) {
        int o = w * 8 + k;
        float2 wv = ((const float2*)(wxw + o * E_DIM))[lane];
        float p = wv.x * aggS[lane * 2] + wv.y * aggS[lane * 2 + 1];
        #pragma unroll
        for (int off = 16; off > 0; off >>= 1) p += __shfl_down_sync(0xffffffffu, p, off);
        if (lane == 0) vS[o] = leaky(p + wxb[o]);
    }
    __syncthreads();
    #pragma unroll
    for (int k = 0; k < 8; k++) {
        int o = w * 8 + k;
        float4 wv = ((const float4*)(wcw + o * 128))[lane];
        int i0 = lane * 4;
        float x0 = (i0 < 64)     ? hsumS[i0]     : vS[i0 - 64];
        float x1 = (i0 + 1 < 64) ? hsumS[i0 + 1] : vS[i0 - 63];
        float x2 = (i0 + 2 < 64) ? hsumS[i0 + 2] : vS[i0 - 62];
        float x3 = (i0 + 3 < 64) ? hsumS[i0 + 3] : vS[i0 - 61];
        float p = wv.x * x0 + wv.y * x1 + wv.z * x2 + wv.w * x3;
        #pragma unroll
        for (int off = 16; off > 0; off >>= 1) p += __shfl_down_sync(0xffffffffu, p, off);
        if (lane == 0) out[b * 192 + o] = leaky(p + wcb[o]);
    }
}

// ---------------------------------------------------------------------------
extern "C" void kernel_launch(void* const* d_in, const int* in_sizes, int n_in,
                              void* d_out, int out_size) {
    const int*   entity_idx = (const int*)d_in[0];
    const int*   adj_e      = (const int*)d_in[1];
    const int*   adj_r      = (const int*)d_in[2];
    const float* E          = (const float*)d_in[3];
    const float* R          = (const float*)d_in[4];
    const float* w1         = (const float*)d_in[5];
    const float* w2         = (const float*)d_in[6];
    const float* w3         = (const float*)d_in[7];
    const float* wxw        = (const float*)d_in[8];
    const float* wxb        = (const float*)d_in[9];
    const float* wcw        = (const float*)d_in[10];
    const float* wcb        = (const float*)d_in[11];
    float* out = (float*)d_out;

    prep_kernel<<<NB_NORM + 1, 256>>>(E, R, w1, w2);
    fused_kernel<<<BSZ, 256>>>(entity_idx, adj_e, adj_r, E, w1, w3,
                               wxw, wxb, wcw, wcb, out);
}